// round 9
// baseline (speedup 1.0000x reference)
#include <cuda_runtime.h>
#include <cstdint>

#define BATCH 8
#define SEQ   1024
#define DIM   768
#define EPS_F 1e-7f

#define BM 128
#define BN 128
#define BK 32
#define PADK 36      // K-major padded k-stride (floats)
#define PADN 140     // N-major padded n-stride: row-pair frag reads conflict-free
#define PADT 132     // transpose-stage stride
#define STAGES 3

#define QK_STAGE_F (2 * BM * PADK)                 // 9216 floats
#define QK_SMEM    (STAGES * QK_STAGE_F * 4)       // 110592 B
#define PV_STAGE_F (BM * PADK + BK * PADN)         // 9088 floats
#define PV_SMEM    (STAGES * PV_STAGE_F * 4)       // 109056 B

// k-permutation within 8-groups: pos(k) = (k&3)*2 + (k>>2)  [0,4,1,5,2,6,3,7]
// inverse: k(pos) = (pos>>1) + (pos&1)*4
__device__ __forceinline__ int pcol(int c) {
    return (c & ~7) | (((c & 3) << 1) + ((c >> 2) & 1));
}

// Scratch (allocation-free rule: __device__ globals)
__device__ float g_Atf[(size_t)BATCH * SEQ * DIM];  // tf32-rounded, DIM k-permuted
__device__ float g_E[(size_t)BATCH * SEQ * SEQ];    // tf32-rounded, col k-permuted
__device__ float g_partial[(size_t)BATCH * SEQ * 32];
__device__ float g_den[(size_t)BATCH * SEQ];

__device__ __forceinline__ uint32_t smem_u32(const void* p) {
    uint32_t a;
    asm("{ .reg .u64 t; cvta.to.shared.u64 t, %1; cvt.u32.u64 %0, t; }" : "=r"(a) : "l"(p));
    return a;
}
__device__ __forceinline__ uint32_t f2tf(float x) {
    uint32_t u; asm("cvt.rna.tf32.f32 %0, %1;" : "=r"(u) : "f"(x)); return u;
}
__device__ __forceinline__ void mma_tf32(float c[4],
                                         uint32_t a0, uint32_t a1, uint32_t a2, uint32_t a3,
                                         uint32_t b0, uint32_t b1) {
    asm("mma.sync.aligned.m16n8k8.row.col.f32.tf32.tf32.f32 "
        "{%0,%1,%2,%3}, {%4,%5,%6,%7}, {%8,%9}, {%0,%1,%2,%3};"
        : "+f"(c[0]), "+f"(c[1]), "+f"(c[2]), "+f"(c[3])
        : "r"(a0), "r"(a1), "r"(a2), "r"(a3), "r"(b0), "r"(b1));
}
__device__ __forceinline__ void cp16(uint32_t saddr, const void* g) {
    asm volatile("cp.async.cg.shared.global [%0], [%1], 16;" :: "r"(saddr), "l"(g));
}
#define CP_COMMIT() asm volatile("cp.async.commit_group;" ::: "memory")
#define CP_WAIT1()  asm volatile("cp.async.wait_group 1;" ::: "memory")

// ---------------------------------------------------------------------------
// Compute cores. k-permuted SMEM => (tq, tq+4) adjacent => LDS.64 fragments.
// ---------------------------------------------------------------------------
#define COMPUTE_KM(AsBuf, BsBuf)                                              \
    _Pragma("unroll")                                                         \
    for (int ks = 0; ks < 4; ks++) {                                          \
        uint2 bq[4];                                                          \
        _Pragma("unroll")                                                     \
        for (int nt = 0; nt < 4; nt++)                                        \
            bq[nt] = *(const uint2*)((const float*)(BsBuf) +                  \
                (nBase + nt * 8 + qid) * PADK + ks * 8 + 2 * tq);             \
        _Pragma("unroll")                                                     \
        for (int mt = 0; mt < 4; mt++) {                                      \
            const float* ap = (const float*)(AsBuf) +                         \
                (mBase + mt * 16 + qid) * PADK + ks * 8 + 2 * tq;             \
            uint2 aL = *(const uint2*)ap;                                     \
            uint2 aH = *(const uint2*)(ap + 8 * PADK);                        \
            _Pragma("unroll")                                                 \
            for (int nt = 0; nt < 4; nt++)                                    \
                mma_tf32(acc[mt][nt], aL.x, aH.x, aL.y, aH.y, bq[nt].x, bq[nt].y); \
        }                                                                     \
    }

#define COMPUTE_NM(AsBuf, VsBuf)                                              \
    _Pragma("unroll")                                                         \
    for (int ks = 0; ks < 4; ks++) {                                          \
        uint32_t bf[4][2];                                                    \
        _Pragma("unroll")                                                     \
        for (int nt = 0; nt < 4; nt++) {                                      \
            const uint32_t* bp = (const uint32_t*)(VsBuf) +                   \
                (ks * 8 + 2 * tq) * PADN + nBase + nt * 8 + qid;              \
            bf[nt][0] = bp[0]; bf[nt][1] = bp[PADN];                          \
        }                                                                     \
        _Pragma("unroll")                                                     \
        for (int mt = 0; mt < 4; mt++) {                                      \
            const float* ap = (const float*)(AsBuf) +                         \
                (mBase + mt * 16 + qid) * PADK + ks * 8 + 2 * tq;             \
            uint2 aL = *(const uint2*)ap;                                     \
            uint2 aH = *(const uint2*)(ap + 8 * PADK);                        \
            _Pragma("unroll")                                                 \
            for (int nt = 0; nt < 4; nt++)                                    \
                mma_tf32(acc[mt][nt], aL.x, aH.x, aL.y, aH.y, bf[nt][0], bf[nt][1]); \
        }                                                                     \
    }

// ---------------------------------------------------------------------------
// Kernel 0: round A to tf32 AND permute the DIM axis within 8-groups.
// ---------------------------------------------------------------------------
__global__ void __launch_bounds__(256) cvt_kernel(const float* __restrict__ A)
{
    size_t i = ((size_t)blockIdx.x * blockDim.x + threadIdx.x) * 4;
    const size_t N = (size_t)BATCH * SEQ * DIM;
    if (i < N) {
        float4 v = *(const float4*)(A + i);
        size_t base = i & ~(size_t)7;
        int odd = (int)((i >> 2) & 1);           // i%8==4 -> odd positions
        float* d = g_Atf + base + odd;
        d[0] = __uint_as_float(f2tf(v.x));
        d[2] = __uint_as_float(f2tf(v.y));
        d[4] = __uint_as_float(f2tf(v.z));
        d[6] = __uint_as_float(f2tf(v.w));
    }
}

// ---------------------------------------------------------------------------
// Kernel 1: E = exp(A A^T) * masks, symmetric (bx >= by), col-permuted stores.
// ---------------------------------------------------------------------------
__global__ void __launch_bounds__(256, 2) qk_exp_mma(const int* __restrict__ mask)
{
    extern __shared__ float dsm[];

    const int bx = blockIdx.x;
    const int by = blockIdx.y;
    if (bx < by) return;
    const bool offdiag = (bx > by);

    const int b       = blockIdx.z;
    const int rowBase = by * BM;
    const int colBase = bx * BN;
    const float* Ab = g_Atf + (size_t)b * SEQ * DIM;
    const int bS = b * SEQ;

    const int tid  = threadIdx.x;
    const int wid  = tid >> 5;
    const int lane = tid & 31;
    const int qid  = lane >> 2;
    const int tq   = lane & 3;
    const int mBase = (wid >> 2) * 64;
    const int nBase = (wid & 3) * 32;
    const int wr   = wid >> 2;
    const int wc   = wid & 3;

    const uint32_t sb = smem_u32(dsm);

    float acc[4][4][4];
    #pragma unroll
    for (int i = 0; i < 4; i++)
        #pragma unroll
        for (int j = 0; j < 4; j++)
            #pragma unroll
            for (int k = 0; k < 4; k++) acc[i][j][k] = 0.f;

    const int NT = DIM / BK;   // 24

    #pragma unroll
    for (int s = 0; s < STAGES - 1; s++) {
        const uint32_t so = s * QK_STAGE_F * 4;
        const int k0 = s * BK;
        #pragma unroll
        for (int l = 0; l < 4; l++) {
            int idx = tid + l * 256;
            int r   = idx >> 3;
            int c4  = (idx & 7) << 2;
            cp16(sb + so + (r * PADK + c4) * 4,
                 Ab + (size_t)(rowBase + r) * DIM + k0 + c4);
            cp16(sb + so + (BM * PADK + r * PADK + c4) * 4,
                 Ab + (size_t)(colBase + r) * DIM + k0 + c4);
        }
        CP_COMMIT();
    }

    for (int it = 0; it < NT; it++) {
        CP_WAIT1();
        __syncthreads();
        {
            const int tn = it + 2;
            if (tn < NT) {
                const uint32_t so = (tn % STAGES) * QK_STAGE_F * 4;
                const int k0 = tn * BK;
                #pragma unroll
                for (int l = 0; l < 4; l++) {
                    int idx = tid + l * 256;
                    int r   = idx >> 3;
                    int c4  = (idx & 7) << 2;
                    cp16(sb + so + (r * PADK + c4) * 4,
                         Ab + (size_t)(rowBase + r) * DIM + k0 + c4);
                    cp16(sb + so + (BM * PADK + r * PADK + c4) * 4,
                         Ab + (size_t)(colBase + r) * DIM + k0 + c4);
                }
            }
            CP_COMMIT();
        }
        const float* As = dsm + (it % STAGES) * QK_STAGE_F;
        const float* Bs = As + BM * PADK;
        COMPUTE_KM(As, Bs);
    }

    __syncthreads();
    float* stage = dsm;

    float cs[4][2];
    #pragma unroll
    for (int nt = 0; nt < 4; nt++) { cs[nt][0] = 0.f; cs[nt][1] = 0.f; }

    #pragma unroll
    for (int mt = 0; mt < 4; mt++) {
        const int rrl = mBase + mt * 16 + qid;
        const int rr  = rowBase + rrl;
        const int prr = pcol(rrl);                 // permuted local row (for transpose)
        const float mr0 = (float)mask[bS + rr];
        const float mr1 = (float)mask[bS + rr + 8];
        float s0 = 0.f, s1 = 0.f;
        #pragma unroll
        for (int nt = 0; nt < 4; nt++) {
            const int ccl = nBase + nt * 8 + tq * 2;   // real local col
            const int cc  = colBase + ccl;             // real global col
            const float mc0 = (float)mask[bS + cc];
            const float mc1 = (float)mask[bS + cc + 1];
            float e00 = __uint_as_float(f2tf(__expf(acc[mt][nt][0]) * mr0 * mc0));
            float e01 = __uint_as_float(f2tf(__expf(acc[mt][nt][1]) * mr0 * mc1));
            float e10 = __uint_as_float(f2tf(__expf(acc[mt][nt][2]) * mr1 * mc0));
            float e11 = __uint_as_float(f2tf(__expf(acc[mt][nt][3]) * mr1 * mc1));
            s0 += e00 + e01;
            s1 += e10 + e11;
            // store E with column positions permuted: cc -> pcol, cc+1 -> pcol+2
            const int pc = colBase + pcol(ccl);
            float* er0 = &g_E[((size_t)bS + rr) * SEQ + pc];
            float* er1 = &g_E[((size_t)bS + rr + 8) * SEQ + pc];
            er0[0] = e00; er0[2] = e01;
            er1[0] = e10; er1[2] = e11;
            if (offdiag) {
                cs[nt][0] += e00 + e10;
                cs[nt][1] += e01 + e11;
                stage[ccl * PADT + prr]           = e00;
                stage[(ccl + 1) * PADT + prr]     = e01;
                stage[ccl * PADT + prr + 8]       = e10;
                stage[(ccl + 1) * PADT + prr + 8] = e11;
            }
        }
        s0 += __shfl_xor_sync(0xffffffffu, s0, 1);
        s0 += __shfl_xor_sync(0xffffffffu, s0, 2);
        s1 += __shfl_xor_sync(0xffffffffu, s1, 1);
        s1 += __shfl_xor_sync(0xffffffffu, s1, 2);
        if (tq == 0) {
            g_partial[((size_t)bS + rr) * 32 + bx * 4 + wc]     = s0;
            g_partial[((size_t)bS + rr + 8) * 32 + bx * 4 + wc] = s1;
        }
    }

    if (offdiag) {
        #pragma unroll
        for (int nt = 0; nt < 4; nt++) {
            #pragma unroll
            for (int h = 0; h < 2; h++) {
                float v = cs[nt][h];
                v += __shfl_xor_sync(0xffffffffu, v, 4);
                v += __shfl_xor_sync(0xffffffffu, v, 8);
                v += __shfl_xor_sync(0xffffffffu, v, 16);
                cs[nt][h] = v;
            }
        }
        if (qid == 0) {
            #pragma unroll
            for (int nt = 0; nt < 4; nt++) {
                const int cc = colBase + nBase + nt * 8 + tq * 2;  // real col ids
                g_partial[((size_t)bS + cc) * 32 + by * 4 + wr]         = cs[nt][0];
                g_partial[((size_t)bS + cc + 1) * 32 + by * 4 + wr]     = cs[nt][1];
                g_partial[((size_t)bS + cc) * 32 + by * 4 + 2 + wr]     = 0.f;
                g_partial[((size_t)bS + cc + 1) * 32 + by * 4 + 2 + wr] = 0.f;
            }
        }
        __syncthreads();
        // transposed tile: rows = real cols; stage columns already hold the
        // permuted row positions -> straight coalesced copy.
        #pragma unroll
        for (int l = 0; l < 16; l++) {
            int idx = tid + l * 256;
            int c   = idx >> 5;
            int r4  = (idx & 31) << 2;
            float4 v = *(float4*)&stage[c * PADT + r4];
            *(float4*)&g_E[((size_t)bS + colBase + c) * SEQ + rowBase + r4] = v;
        }
    }
}

// ---------------------------------------------------------------------------
__global__ void reduce_den_kernel()
{
    int i = blockIdx.x * blockDim.x + threadIdx.x;
    if (i < BATCH * SEQ) {
        float s = EPS_F;
        #pragma unroll
        for (int j = 0; j < 32; j++) s += g_partial[(size_t)i * 32 + j];
        g_den[i] = s;
    }
}

// ---------------------------------------------------------------------------
// Kernel 3: out = (E @ A) / den.  V rows permuted at cp.async source to match
// E's permuted k columns.  NOTE: V's N axis (D) is ALSO permuted (g_Atf), so
// the epilogue un-permutes: C position pair (tq*2, tq*2+1) -> real cols
// (base+tq, base+tq+4).
// ---------------------------------------------------------------------------
__global__ void __launch_bounds__(256, 2) pv_mma(float* __restrict__ out)
{
    extern __shared__ float dsm[];

    const int b       = blockIdx.z;
    const int rowBase = blockIdx.y * BM;
    const int colBase = blockIdx.x * BN;
    const float* Ab = g_Atf + (size_t)b * SEQ * DIM;
    const float* Eb = g_E   + (size_t)b * SEQ * SEQ;
    const int bS = b * SEQ;

    const int tid  = threadIdx.x;
    const int wid  = tid >> 5;
    const int lane = tid & 31;
    const int qid  = lane >> 2;
    const int tq   = lane & 3;
    const int mBase = (wid >> 2) * 64;
    const int nBase = (wid & 3) * 32;

    const uint32_t sb = smem_u32(dsm);

    // permuted V source rows: stage row vr holds A row k0+invp(vr)
    const float* srcV[4];
    uint32_t dstV[4];
    #pragma unroll
    for (int l = 0; l < 4; l++) {
        int idx = tid + l * 256;
        int vr  = idx >> 5;                    // 0..31
        int vc4 = (idx & 31) << 2;
        int kk  = (vr & ~7) | ((vr >> 1) & 3) | ((vr & 1) << 2);  // invp within group
        srcV[l] = Ab + (size_t)kk * DIM + colBase + vc4;
        dstV[l] = (uint32_t)((BM * PADK + vr * PADN + vc4) * 4);
    }

    float acc[4][4][4];
    #pragma unroll
    for (int i = 0; i < 4; i++)
        #pragma unroll
        for (int j = 0; j < 4; j++)
            #pragma unroll
            for (int k = 0; k < 4; k++) acc[i][j][k] = 0.f;

    const int NT = SEQ / BK;   // 32

    #pragma unroll
    for (int s = 0; s < STAGES - 1; s++) {
        const uint32_t so = s * PV_STAGE_F * 4;
        const int k0 = s * BK;
        #pragma unroll
        for (int l = 0; l < 4; l++) {
            int idx = tid + l * 256;
            int r   = idx >> 3;
            int c4  = (idx & 7) << 2;
            cp16(sb + so + (r * PADK + c4) * 4,
                 Eb + (size_t)(rowBase + r) * SEQ + k0 + c4);
            cp16(sb + so + dstV[l], srcV[l] + (size_t)k0 * DIM);
        }
        CP_COMMIT();
    }

    for (int it = 0; it < NT; it++) {
        CP_WAIT1();
        __syncthreads();
        {
            const int tn = it + 2;
            if (tn < NT) {
                const uint32_t so = (tn % STAGES) * PV_STAGE_F * 4;
                const int k0 = tn * BK;
                #pragma unroll
                for (int l = 0; l < 4; l++) {
                    int idx = tid + l * 256;
                    int r   = idx >> 3;
                    int c4  = (idx & 7) << 2;
                    cp16(sb + so + (r * PADK + c4) * 4,
                         Eb + (size_t)(rowBase + r) * SEQ + k0 + c4);
                    cp16(sb + so + dstV[l], srcV[l] + (size_t)k0 * DIM);
                }
            }
            CP_COMMIT();
        }
        const float* Es = dsm + (it % STAGES) * PV_STAGE_F;
        const float* Vs = Es + BM * PADK;
        COMPUTE_NM(Es, Vs);
    }

    // Epilogue: scale by 1/den and UN-PERMUTE columns.
    // C position pair (tq*2, tq*2+1) within each n8 tile holds real columns
    // (tq, tq+4) of that tile (invp of the 8-group permutation).
    #pragma unroll
    for (int mt = 0; mt < 4; mt++) {
        const int rr = rowBase + mBase + mt * 16 + qid;
        const float inv0 = 1.0f / g_den[bS + rr];
        const float inv1 = 1.0f / g_den[bS + rr + 8];
        float* o0 = out + ((size_t)bS + rr) * DIM;
        float* o1 = out + ((size_t)bS + rr + 8) * DIM;
        #pragma unroll
        for (int nt = 0; nt < 4; nt++) {
            const int base = colBase + nBase + nt * 8;
            o0[base + tq]     = acc[mt][nt][0] * inv0;
            o0[base + tq + 4] = acc[mt][nt][1] * inv0;
            o1[base + tq]     = acc[mt][nt][2] * inv1;
            o1[base + tq + 4] = acc[mt][nt][3] * inv1;
        }
    }
}

// ---------------------------------------------------------------------------
extern "C" void kernel_launch(void* const* d_in, const int* in_sizes, int n_in,
                              void* d_out, int out_size)
{
    const float* A    = (const float*)d_in[0];
    const int*   mask = (const int*)d_in[1];
    float*       out  = (float*)d_out;

    cudaFuncSetAttribute(qk_exp_mma, cudaFuncAttributeMaxDynamicSharedMemorySize, QK_SMEM);
    cudaFuncSetAttribute(pv_mma,     cudaFuncAttributeMaxDynamicSharedMemorySize, PV_SMEM);

    const size_t nA = (size_t)BATCH * SEQ * DIM;
    cvt_kernel<<<(unsigned)((nA / 4 + 255) / 256), 256>>>(A);

    dim3 g1(SEQ / BN, SEQ / BM, BATCH);
    qk_exp_mma<<<g1, 256, QK_SMEM>>>(mask);

    reduce_den_kernel<<<(BATCH * SEQ + 255) / 256, 256>>>();

    dim3 g2(DIM / BN, SEQ / BM, BATCH);
    pv_mma<<<g2, 256, PV_SMEM>>>(out);
}

// round 11
// speedup vs baseline: 1.0280x; 1.0280x over previous
#include <cuda_runtime.h>
#include <cstdint>

#define BATCH 8
#define SEQ   1024
#define DIM   768
#define EPS_F 1e-7f

// ---------------- qk geometry: 128x128 block, 8 warps 64x32, BK=32 ----------
#define QK_STAGES 3
#define QK_STAGE_B 32768                       // As 16KB + Bs 16KB, stride 32 words
#define QK_SMEM   (QK_STAGES * QK_STAGE_B)     // 98304
#define PADT 132                               // qk transpose-stage stride

// ---------------- pv geometry: 128x256 block, 8 warps 64x64, BK=32 ----------
#define PV_STAGES 4
#define PADN 260                               // V n-stride (floats)
#define PV_E_B   16384                         // Es: 128 rows x 128B
#define PV_V_B   (32 * PADN * 4)               // 33280
#define PV_STAGE_B (PV_E_B + PV_V_B)           // 49664
#define PV_SMEM  (PV_STAGES * PV_STAGE_B)      // 198656

// k-permutation within 8-groups: pos(k) = (k&3)*2 + (k>>2)  [0,4,1,5,2,6,3,7]
__device__ __forceinline__ int pcol(int c) {
    return (c & ~7) | (((c & 3) << 1) + ((c >> 2) & 1));
}

// Scratch (allocation-free rule: __device__ globals)
__device__ float g_Atf[(size_t)BATCH * SEQ * DIM];  // tf32-rounded, DIM k-permuted
__device__ float g_E[(size_t)BATCH * SEQ * SEQ];    // tf32-rounded, col k-permuted
__device__ float g_partial[(size_t)BATCH * SEQ * 32];
__device__ float g_den[(size_t)BATCH * SEQ];

__device__ __forceinline__ uint32_t smem_u32(const void* p) {
    uint32_t a;
    asm("{ .reg .u64 t; cvta.to.shared.u64 t, %1; cvt.u32.u64 %0, t; }" : "=r"(a) : "l"(p));
    return a;
}
__device__ __forceinline__ uint32_t f2tf(float x) {
    uint32_t u; asm("cvt.rna.tf32.f32 %0, %1;" : "=r"(u) : "f"(x)); return u;
}
__device__ __forceinline__ void mma_tf32(float c[4],
                                         uint32_t a0, uint32_t a1, uint32_t a2, uint32_t a3,
                                         uint32_t b0, uint32_t b1) {
    asm("mma.sync.aligned.m16n8k8.row.col.f32.tf32.tf32.f32 "
        "{%0,%1,%2,%3}, {%4,%5,%6,%7}, {%8,%9}, {%0,%1,%2,%3};"
        : "+f"(c[0]), "+f"(c[1]), "+f"(c[2]), "+f"(c[3])
        : "r"(a0), "r"(a1), "r"(a2), "r"(a3), "r"(b0), "r"(b1));
}
__device__ __forceinline__ void cp16(uint32_t saddr, const void* g) {
    asm volatile("cp.async.cg.shared.global [%0], [%1], 16;" :: "r"(saddr), "l"(g));
}
#define CP_COMMIT() asm volatile("cp.async.commit_group;" ::: "memory")
#define CP_WAIT1()  asm volatile("cp.async.wait_group 1;" ::: "memory")
#define CP_WAIT2()  asm volatile("cp.async.wait_group 2;" ::: "memory")

// swizzled fragment byte-offset inside a [rows][32 words] tile:
//   physical chunk = (2ks + (tq>>1)) ^ ((row&3)<<1), +8B if tq odd
#define SWOFF(row, ks) \
    ((uint32_t)(row) * 128u + (uint32_t)((((2*(ks)) + cb) ^ swz) << 4) + w8)

// ---------------------------------------------------------------------------
// Kernel 0: round A to tf32 AND permute the DIM axis within 8-groups.
// ---------------------------------------------------------------------------
__global__ void __launch_bounds__(256) cvt_kernel(const float* __restrict__ A)
{
    size_t i = ((size_t)blockIdx.x * blockDim.x + threadIdx.x) * 4;
    const size_t N = (size_t)BATCH * SEQ * DIM;
    if (i < N) {
        float4 v = *(const float4*)(A + i);
        size_t base = i & ~(size_t)7;
        int odd = (int)((i >> 2) & 1);
        float* d = g_Atf + base + odd;
        d[0] = __uint_as_float(f2tf(v.x));
        d[2] = __uint_as_float(f2tf(v.y));
        d[4] = __uint_as_float(f2tf(v.z));
        d[6] = __uint_as_float(f2tf(v.w));
    }
}

// ---------------------------------------------------------------------------
// Kernel 1: E = exp(A A^T) * masks, symmetric (bx >= by).  Swizzled tiles,
// LDS.64 fragments, col-permuted E stores.
// ---------------------------------------------------------------------------
__global__ void __launch_bounds__(256, 2) qk_exp_mma(const int* __restrict__ mask)
{
    extern __shared__ float dsm[];

    const int bx = blockIdx.x;
    const int by = blockIdx.y;
    if (bx < by) return;
    const bool offdiag = (bx > by);

    const int b       = blockIdx.z;
    const int rowBase = by * 128;
    const int colBase = bx * 128;
    const float* Ab = g_Atf + (size_t)b * SEQ * DIM;
    const int bS = b * SEQ;

    const int tid  = threadIdx.x;
    const int wid  = tid >> 5;
    const int lane = tid & 31;
    const int qid  = lane >> 2;
    const int tq   = lane & 3;
    const int mBase = (wid >> 2) * 64;
    const int nBase = (wid & 3) * 32;
    const int wr   = wid >> 2;
    const int wc   = wid & 3;

    const uint32_t cb  = (uint32_t)(tq >> 1);
    const uint32_t w8  = (uint32_t)((tq & 1) * 8);
    const uint32_t swz = (uint32_t)((qid & 3) << 1);

    const uint32_t sb = smem_u32(dsm);

    const float* gA[4]; const float* gB[4]; uint32_t dstT[4];
    #pragma unroll
    for (int l = 0; l < 4; l++) {
        int idx = tid + l * 256;
        int r   = idx >> 3;
        int c   = idx & 7;
        dstT[l] = (uint32_t)(r * 128 + ((c ^ ((r & 3) << 1)) << 4));
        gA[l]   = Ab + (size_t)(rowBase + r) * DIM + c * 4;
        gB[l]   = Ab + (size_t)(colBase + r) * DIM + c * 4;
    }

    float acc[4][4][4];
    #pragma unroll
    for (int i = 0; i < 4; i++)
        #pragma unroll
        for (int j = 0; j < 4; j++)
            #pragma unroll
            for (int k = 0; k < 4; k++) acc[i][j][k] = 0.f;

    const int NT = DIM / 32;   // 24

    #pragma unroll
    for (int s = 0; s < QK_STAGES - 1; s++) {
        const uint32_t so = s * QK_STAGE_B;
        const int k0 = s * 32;
        #pragma unroll
        for (int l = 0; l < 4; l++) {
            cp16(sb + so + dstT[l], gA[l] + k0);
            cp16(sb + so + 16384 + dstT[l], gB[l] + k0);
        }
        CP_COMMIT();
    }

    for (int it = 0; it < NT; it++) {
        CP_WAIT1();
        __syncthreads();
        {
            const int tn = it + 2;
            if (tn < NT) {
                const uint32_t so = (tn % QK_STAGES) * QK_STAGE_B;
                const int k0 = tn * 32;
                #pragma unroll
                for (int l = 0; l < 4; l++) {
                    cp16(sb + so + dstT[l], gA[l] + k0);
                    cp16(sb + so + 16384 + dstT[l], gB[l] + k0);
                }
            }
            CP_COMMIT();
        }
        const char* As = (const char*)dsm + (it % QK_STAGES) * QK_STAGE_B;
        const char* Bs = As + 16384;
        #pragma unroll
        for (int ks = 0; ks < 4; ks++) {
            uint2 bq[4];
            #pragma unroll
            for (int nt = 0; nt < 4; nt++)
                bq[nt] = *(const uint2*)(Bs + SWOFF(nBase + nt * 8 + qid, ks));
            #pragma unroll
            for (int mt = 0; mt < 4; mt++) {
                const char* ap = As + SWOFF(mBase + mt * 16 + qid, ks);
                uint2 aL = *(const uint2*)ap;
                uint2 aH = *(const uint2*)(ap + 8 * 128);
                #pragma unroll
                for (int nt = 0; nt < 4; nt++)
                    mma_tf32(acc[mt][nt], aL.x, aH.x, aL.y, aH.y, bq[nt].x, bq[nt].y);
            }
        }
    }

    __syncthreads();
    float* stage = dsm;

    float cs[4][2];
    #pragma unroll
    for (int nt = 0; nt < 4; nt++) { cs[nt][0] = 0.f; cs[nt][1] = 0.f; }

    #pragma unroll
    for (int mt = 0; mt < 4; mt++) {
        const int rrl = mBase + mt * 16 + qid;
        const int rr  = rowBase + rrl;
        const int prr = pcol(rrl);
        const float mr0 = (float)mask[bS + rr];
        const float mr1 = (float)mask[bS + rr + 8];
        float s0 = 0.f, s1 = 0.f;
        #pragma unroll
        for (int nt = 0; nt < 4; nt++) {
            const int ccl = nBase + nt * 8 + tq * 2;
            const int cc  = colBase + ccl;
            const float mc0 = (float)mask[bS + cc];
            const float mc1 = (float)mask[bS + cc + 1];
            float e00 = __uint_as_float(f2tf(__expf(acc[mt][nt][0]) * mr0 * mc0));
            float e01 = __uint_as_float(f2tf(__expf(acc[mt][nt][1]) * mr0 * mc1));
            float e10 = __uint_as_float(f2tf(__expf(acc[mt][nt][2]) * mr1 * mc0));
            float e11 = __uint_as_float(f2tf(__expf(acc[mt][nt][3]) * mr1 * mc1));
            s0 += e00 + e01;
            s1 += e10 + e11;
            const int pc = colBase + pcol(ccl);
            float* er0 = &g_E[((size_t)bS + rr) * SEQ + pc];
            float* er1 = &g_E[((size_t)bS + rr + 8) * SEQ + pc];
            er0[0] = e00; er0[2] = e01;
            er1[0] = e10; er1[2] = e11;
            if (offdiag) {
                cs[nt][0] += e00 + e10;
                cs[nt][1] += e01 + e11;
                stage[ccl * PADT + prr]           = e00;
                stage[(ccl + 1) * PADT + prr]     = e01;
                stage[ccl * PADT + prr + 8]       = e10;
                stage[(ccl + 1) * PADT + prr + 8] = e11;
            }
        }
        s0 += __shfl_xor_sync(0xffffffffu, s0, 1);
        s0 += __shfl_xor_sync(0xffffffffu, s0, 2);
        s1 += __shfl_xor_sync(0xffffffffu, s1, 1);
        s1 += __shfl_xor_sync(0xffffffffu, s1, 2);
        if (tq == 0) {
            g_partial[((size_t)bS + rr) * 32 + bx * 4 + wc]     = s0;
            g_partial[((size_t)bS + rr + 8) * 32 + bx * 4 + wc] = s1;
        }
    }

    if (offdiag) {
        #pragma unroll
        for (int nt = 0; nt < 4; nt++) {
            #pragma unroll
            for (int h = 0; h < 2; h++) {
                float v = cs[nt][h];
                v += __shfl_xor_sync(0xffffffffu, v, 4);
                v += __shfl_xor_sync(0xffffffffu, v, 8);
                v += __shfl_xor_sync(0xffffffffu, v, 16);
                cs[nt][h] = v;
            }
        }
        if (qid == 0) {
            #pragma unroll
            for (int nt = 0; nt < 4; nt++) {
                const int cc = colBase + nBase + nt * 8 + tq * 2;
                g_partial[((size_t)bS + cc) * 32 + by * 4 + wr]         = cs[nt][0];
                g_partial[((size_t)bS + cc + 1) * 32 + by * 4 + wr]     = cs[nt][1];
                g_partial[((size_t)bS + cc) * 32 + by * 4 + 2 + wr]     = 0.f;
                g_partial[((size_t)bS + cc + 1) * 32 + by * 4 + 2 + wr] = 0.f;
            }
        }
        __syncthreads();
        #pragma unroll
        for (int l = 0; l < 16; l++) {
            int idx = tid + l * 256;
            int c   = idx >> 5;
            int r4  = (idx & 31) << 2;
            float4 v = *(float4*)&stage[c * PADT + r4];
            *(float4*)&g_E[((size_t)bS + colBase + c) * SEQ + rowBase + r4] = v;
        }
    }
}

// ---------------------------------------------------------------------------
__global__ void reduce_den_kernel()
{
    int i = blockIdx.x * blockDim.x + threadIdx.x;
    if (i < BATCH * SEQ) {
        float s = EPS_F;
        #pragma unroll
        for (int j = 0; j < 32; j++) s += g_partial[(size_t)i * 32 + j];
        g_den[i] = s;
    }
}

// ---------------------------------------------------------------------------
// Kernel 3: out = (E @ A) / den.  Block 128x256, 8 warps 64x64, 4 stages.
// E swizzled + LDS.64; V rows permuted at cp.async source (FULL 64 chunks/row
// coverage: 8 chunks/thread); epilogue un-permutes output columns.
// ---------------------------------------------------------------------------
__global__ void __launch_bounds__(256, 1) pv_mma(float* __restrict__ out)
{
    extern __shared__ float dsm[];

    const int b       = blockIdx.z;
    const int rowBase = blockIdx.y * 128;
    const int colBase = blockIdx.x * 256;
    const float* Ab = g_Atf + (size_t)b * SEQ * DIM;
    const float* Eb = g_E   + (size_t)b * SEQ * SEQ;
    const int bS = b * SEQ;

    const int tid  = threadIdx.x;
    const int wid  = tid >> 5;
    const int lane = tid & 31;
    const int qid  = lane >> 2;
    const int tq   = lane & 3;
    const int mBase = (wid >> 2) * 64;
    const int nBase = (wid & 3) * 64;

    const uint32_t cb  = (uint32_t)(tq >> 1);
    const uint32_t w8  = (uint32_t)((tq & 1) * 8);
    const uint32_t swz = (uint32_t)((qid & 3) << 1);

    const uint32_t sb = smem_u32(dsm);

    // E loader: 4 chunks/thread (128 rows x 8 chunks)
    const float* gE[4]; uint32_t dstE[4];
    #pragma unroll
    for (int l = 0; l < 4; l++) {
        int idx = tid + l * 256;
        int r   = idx >> 3;
        int c   = idx & 7;
        dstE[l] = (uint32_t)(r * 128 + ((c ^ ((r & 3) << 1)) << 4));
        gE[l]   = Eb + (size_t)(rowBase + r) * SEQ + c * 4;
    }
    // V loader: 8 chunks/thread (32 rows x 64 chunks), rows k-permuted at src.
    // vr = (tid>>6) + 4l (exact: tid&63 has no carry into bit 6), vc = tid&63.
    const int vr0 = tid >> 6;              // 0..3
    const int vc  = tid & 63;              // 0..63
    const float* gVbase = Ab + colBase + vc * 4;
    uint32_t voff[8], dstV[8];
    #pragma unroll
    for (int l = 0; l < 8; l++) {
        int vr = vr0 + 4 * l;              // 0..31
        int kk = (vr & ~7) | ((vr >> 1) & 3) | ((vr & 1) << 2);  // invp
        voff[l] = (uint32_t)(kk * DIM);
        dstV[l] = (uint32_t)(PV_E_B + vr * (PADN * 4) + vc * 16);
    }

    float acc[4][8][4];
    #pragma unroll
    for (int i = 0; i < 4; i++)
        #pragma unroll
        for (int j = 0; j < 8; j++)
            #pragma unroll
            for (int k = 0; k < 4; k++) acc[i][j][k] = 0.f;

    const int NT = SEQ / 32;   // 32

    #pragma unroll
    for (int s = 0; s < PV_STAGES - 1; s++) {
        const uint32_t so = s * PV_STAGE_B;
        const int k0 = s * 32;
        #pragma unroll
        for (int l = 0; l < 4; l++) cp16(sb + so + dstE[l], gE[l] + k0);
        #pragma unroll
        for (int l = 0; l < 8; l++)
            cp16(sb + so + dstV[l], gVbase + voff[l] + (size_t)k0 * DIM);
        CP_COMMIT();
    }

    for (int it = 0; it < NT; it++) {
        CP_WAIT2();
        __syncthreads();
        {
            const int tn = it + 3;
            if (tn < NT) {
                const uint32_t so = (tn % PV_STAGES) * PV_STAGE_B;
                const int k0 = tn * 32;
                #pragma unroll
                for (int l = 0; l < 4; l++) cp16(sb + so + dstE[l], gE[l] + k0);
                #pragma unroll
                for (int l = 0; l < 8; l++)
                    cp16(sb + so + dstV[l], gVbase + voff[l] + (size_t)k0 * DIM);
            }
            CP_COMMIT();
        }
        const char* Es = (const char*)dsm + (it % PV_STAGES) * PV_STAGE_B;
        const float* Vs = (const float*)(Es + PV_E_B);
        #pragma unroll
        for (int ks = 0; ks < 4; ks++) {
            uint32_t bf[8][2];
            #pragma unroll
            for (int nt = 0; nt < 8; nt++) {
                const uint32_t* bp = (const uint32_t*)Vs +
                    (ks * 8 + 2 * tq) * PADN + nBase + nt * 8 + qid;
                bf[nt][0] = bp[0]; bf[nt][1] = bp[PADN];
            }
            #pragma unroll
            for (int mt = 0; mt < 4; mt++) {
                const char* ap = Es + SWOFF(mBase + mt * 16 + qid, ks);
                uint2 aL = *(const uint2*)ap;
                uint2 aH = *(const uint2*)(ap + 8 * 128);
                #pragma unroll
                for (int nt = 0; nt < 8; nt++)
                    mma_tf32(acc[mt][nt], aL.x, aH.x, aL.y, aH.y, bf[nt][0], bf[nt][1]);
            }
        }
    }

    // Epilogue: scale by 1/den; un-permute columns (positions (2tq,2tq+1)
    // within each n8 tile hold real columns (tq, tq+4)).
    #pragma unroll
    for (int mt = 0; mt < 4; mt++) {
        const int rr = rowBase + mBase + mt * 16 + qid;
        const float inv0 = 1.0f / g_den[bS + rr];
        const float inv1 = 1.0f / g_den[bS + rr + 8];
        float* o0 = out + ((size_t)bS + rr) * DIM;
        float* o1 = out + ((size_t)bS + rr + 8) * DIM;
        #pragma unroll
        for (int nt = 0; nt < 8; nt++) {
            const int base = colBase + nBase + nt * 8;
            o0[base + tq]     = acc[mt][nt][0] * inv0;
            o0[base + tq + 4] = acc[mt][nt][1] * inv0;
            o1[base + tq]     = acc[mt][nt][2] * inv1;
            o1[base + tq + 4] = acc[mt][nt][3] * inv1;
        }
    }
}

// ---------------------------------------------------------------------------
extern "C" void kernel_launch(void* const* d_in, const int* in_sizes, int n_in,
                              void* d_out, int out_size)
{
    const float* A    = (const float*)d_in[0];
    const int*   mask = (const int*)d_in[1];
    float*       out  = (float*)d_out;

    cudaFuncSetAttribute(qk_exp_mma, cudaFuncAttributeMaxDynamicSharedMemorySize, QK_SMEM);
    cudaFuncSetAttribute(pv_mma,     cudaFuncAttributeMaxDynamicSharedMemorySize, PV_SMEM);

    const size_t nA = (size_t)BATCH * SEQ * DIM;
    cvt_kernel<<<(unsigned)((nA / 4 + 255) / 256), 256>>>(A);

    dim3 g1(SEQ / 128, SEQ / 128, BATCH);   // triangle via early exit
    qk_exp_mma<<<g1, 256, QK_SMEM>>>(mask);

    reduce_den_kernel<<<(BATCH * SEQ + 255) / 256, 256>>>();

    dim3 g2(DIM / 256, SEQ / 128, BATCH);   // 3 x 8 x 8
    pv_mma<<<g2, 256, PV_SMEM>>>(out);
}

// round 12
// speedup vs baseline: 1.1839x; 1.1516x over previous
#include <cuda_runtime.h>
#include <cstdint>

#define BATCH 8
#define SEQ   1024
#define DIM   768
#define EPS_F 1e-7f

// ---------------- qk geometry: 128x128 block, 8 warps 64x32, BK=32 ----------
#define QK_STAGES 3
#define QK_STAGE_B 32768                       // As 16KB + Bs 16KB, stride 32 words
#define QK_SMEM   (QK_STAGES * QK_STAGE_B)     // 98304
#define PADT 132                               // qk transpose-stage stride

// ---------------- pv geometry: 128x128 block, 8 warps 64x32, BK=32, 2 CTA ---
#define PV_STAGES 3
#define PADN 140                               // V n-stride: scalar frags conflict-free
#define PV_E_B   16384                         // Es: 128 rows x 128B swizzled
#define PV_V_B   (32 * PADN * 4)               // 17920
#define PV_STAGE_B (PV_E_B + PV_V_B)           // 34304
#define PV_SMEM  (PV_STAGES * PV_STAGE_B)      // 102912 -> 2 CTAs/SM

// k-permutation within 8-groups: pos(k) = (k&3)*2 + (k>>2)  [0,4,1,5,2,6,3,7]
__device__ __forceinline__ int pcol(int c) {
    return (c & ~7) | (((c & 3) << 1) + ((c >> 2) & 1));
}

// Scratch (allocation-free rule: __device__ globals)
__device__ float g_Atf[(size_t)BATCH * SEQ * DIM];  // tf32-rounded, DIM k-permuted
__device__ float g_E[(size_t)BATCH * SEQ * SEQ];    // tf32-rounded, col k-permuted
__device__ float g_partial[(size_t)BATCH * SEQ * 32];
__device__ float g_den[(size_t)BATCH * SEQ];

__device__ __forceinline__ uint32_t smem_u32(const void* p) {
    uint32_t a;
    asm("{ .reg .u64 t; cvta.to.shared.u64 t, %1; cvt.u32.u64 %0, t; }" : "=r"(a) : "l"(p));
    return a;
}
__device__ __forceinline__ uint32_t f2tf(float x) {
    uint32_t u; asm("cvt.rna.tf32.f32 %0, %1;" : "=r"(u) : "f"(x)); return u;
}
__device__ __forceinline__ void mma_tf32(float c[4],
                                         uint32_t a0, uint32_t a1, uint32_t a2, uint32_t a3,
                                         uint32_t b0, uint32_t b1) {
    asm("mma.sync.aligned.m16n8k8.row.col.f32.tf32.tf32.f32 "
        "{%0,%1,%2,%3}, {%4,%5,%6,%7}, {%8,%9}, {%0,%1,%2,%3};"
        : "+f"(c[0]), "+f"(c[1]), "+f"(c[2]), "+f"(c[3])
        : "r"(a0), "r"(a1), "r"(a2), "r"(a3), "r"(b0), "r"(b1));
}
__device__ __forceinline__ void cp16(uint32_t saddr, const void* g) {
    asm volatile("cp.async.cg.shared.global [%0], [%1], 16;" :: "r"(saddr), "l"(g));
}
#define CP_COMMIT() asm volatile("cp.async.commit_group;" ::: "memory")
#define CP_WAIT1()  asm volatile("cp.async.wait_group 1;" ::: "memory")

// swizzled fragment byte-offset inside a [rows][32 words] tile:
//   physical chunk = (2ks + (tq>>1)) ^ ((row&3)<<1), +8B if tq odd
#define SWOFF(row, ks) \
    ((uint32_t)(row) * 128u + (uint32_t)((((2*(ks)) + cb) ^ swz) << 4) + w8)

// ---------------------------------------------------------------------------
// Kernel 0: round A to tf32 AND permute the DIM axis within 8-groups.
// ---------------------------------------------------------------------------
__global__ void __launch_bounds__(256) cvt_kernel(const float* __restrict__ A)
{
    size_t i = ((size_t)blockIdx.x * blockDim.x + threadIdx.x) * 4;
    const size_t N = (size_t)BATCH * SEQ * DIM;
    if (i < N) {
        float4 v = *(const float4*)(A + i);
        size_t base = i & ~(size_t)7;
        int odd = (int)((i >> 2) & 1);
        float* d = g_Atf + base + odd;
        d[0] = __uint_as_float(f2tf(v.x));
        d[2] = __uint_as_float(f2tf(v.y));
        d[4] = __uint_as_float(f2tf(v.z));
        d[6] = __uint_as_float(f2tf(v.w));
    }
}

// ---------------------------------------------------------------------------
// Kernel 1: E = exp(A A^T) * masks, symmetric (bx >= by).  Swizzled tiles,
// LDS.64 fragments, col-permuted E stores.  (unchanged from passing round)
// ---------------------------------------------------------------------------
__global__ void __launch_bounds__(256, 2) qk_exp_mma(const int* __restrict__ mask)
{
    extern __shared__ float dsm[];

    const int bx = blockIdx.x;
    const int by = blockIdx.y;
    if (bx < by) return;
    const bool offdiag = (bx > by);

    const int b       = blockIdx.z;
    const int rowBase = by * 128;
    const int colBase = bx * 128;
    const float* Ab = g_Atf + (size_t)b * SEQ * DIM;
    const int bS = b * SEQ;

    const int tid  = threadIdx.x;
    const int wid  = tid >> 5;
    const int lane = tid & 31;
    const int qid  = lane >> 2;
    const int tq   = lane & 3;
    const int mBase = (wid >> 2) * 64;
    const int nBase = (wid & 3) * 32;
    const int wr   = wid >> 2;
    const int wc   = wid & 3;

    const uint32_t cb  = (uint32_t)(tq >> 1);
    const uint32_t w8  = (uint32_t)((tq & 1) * 8);
    const uint32_t swz = (uint32_t)((qid & 3) << 1);

    const uint32_t sb = smem_u32(dsm);

    const float* gA[4]; const float* gB[4]; uint32_t dstT[4];
    #pragma unroll
    for (int l = 0; l < 4; l++) {
        int idx = tid + l * 256;
        int r   = idx >> 3;
        int c   = idx & 7;
        dstT[l] = (uint32_t)(r * 128 + ((c ^ ((r & 3) << 1)) << 4));
        gA[l]   = Ab + (size_t)(rowBase + r) * DIM + c * 4;
        gB[l]   = Ab + (size_t)(colBase + r) * DIM + c * 4;
    }

    float acc[4][4][4];
    #pragma unroll
    for (int i = 0; i < 4; i++)
        #pragma unroll
        for (int j = 0; j < 4; j++)
            #pragma unroll
            for (int k = 0; k < 4; k++) acc[i][j][k] = 0.f;

    const int NT = DIM / 32;   // 24

    #pragma unroll
    for (int s = 0; s < QK_STAGES - 1; s++) {
        const uint32_t so = s * QK_STAGE_B;
        const int k0 = s * 32;
        #pragma unroll
        for (int l = 0; l < 4; l++) {
            cp16(sb + so + dstT[l], gA[l] + k0);
            cp16(sb + so + 16384 + dstT[l], gB[l] + k0);
        }
        CP_COMMIT();
    }

    for (int it = 0; it < NT; it++) {
        CP_WAIT1();
        __syncthreads();
        {
            const int tn = it + 2;
            if (tn < NT) {
                const uint32_t so = (tn % QK_STAGES) * QK_STAGE_B;
                const int k0 = tn * 32;
                #pragma unroll
                for (int l = 0; l < 4; l++) {
                    cp16(sb + so + dstT[l], gA[l] + k0);
                    cp16(sb + so + 16384 + dstT[l], gB[l] + k0);
                }
            }
            CP_COMMIT();
        }
        const char* As = (const char*)dsm + (it % QK_STAGES) * QK_STAGE_B;
        const char* Bs = As + 16384;
        #pragma unroll
        for (int ks = 0; ks < 4; ks++) {
            uint2 bq[4];
            #pragma unroll
            for (int nt = 0; nt < 4; nt++)
                bq[nt] = *(const uint2*)(Bs + SWOFF(nBase + nt * 8 + qid, ks));
            #pragma unroll
            for (int mt = 0; mt < 4; mt++) {
                const char* ap = As + SWOFF(mBase + mt * 16 + qid, ks);
                uint2 aL = *(const uint2*)ap;
                uint2 aH = *(const uint2*)(ap + 8 * 128);
                #pragma unroll
                for (int nt = 0; nt < 4; nt++)
                    mma_tf32(acc[mt][nt], aL.x, aH.x, aL.y, aH.y, bq[nt].x, bq[nt].y);
            }
        }
    }

    __syncthreads();
    float* stage = dsm;

    float cs[4][2];
    #pragma unroll
    for (int nt = 0; nt < 4; nt++) { cs[nt][0] = 0.f; cs[nt][1] = 0.f; }

    #pragma unroll
    for (int mt = 0; mt < 4; mt++) {
        const int rrl = mBase + mt * 16 + qid;
        const int rr  = rowBase + rrl;
        const int prr = pcol(rrl);
        const float mr0 = (float)mask[bS + rr];
        const float mr1 = (float)mask[bS + rr + 8];
        float s0 = 0.f, s1 = 0.f;
        #pragma unroll
        for (int nt = 0; nt < 4; nt++) {
            const int ccl = nBase + nt * 8 + tq * 2;
            const int cc  = colBase + ccl;
            const float mc0 = (float)mask[bS + cc];
            const float mc1 = (float)mask[bS + cc + 1];
            float e00 = __uint_as_float(f2tf(__expf(acc[mt][nt][0]) * mr0 * mc0));
            float e01 = __uint_as_float(f2tf(__expf(acc[mt][nt][1]) * mr0 * mc1));
            float e10 = __uint_as_float(f2tf(__expf(acc[mt][nt][2]) * mr1 * mc0));
            float e11 = __uint_as_float(f2tf(__expf(acc[mt][nt][3]) * mr1 * mc1));
            s0 += e00 + e01;
            s1 += e10 + e11;
            const int pc = colBase + pcol(ccl);
            float* er0 = &g_E[((size_t)bS + rr) * SEQ + pc];
            float* er1 = &g_E[((size_t)bS + rr + 8) * SEQ + pc];
            er0[0] = e00; er0[2] = e01;
            er1[0] = e10; er1[2] = e11;
            if (offdiag) {
                cs[nt][0] += e00 + e10;
                cs[nt][1] += e01 + e11;
                stage[ccl * PADT + prr]           = e00;
                stage[(ccl + 1) * PADT + prr]     = e01;
                stage[ccl * PADT + prr + 8]       = e10;
                stage[(ccl + 1) * PADT + prr + 8] = e11;
            }
        }
        s0 += __shfl_xor_sync(0xffffffffu, s0, 1);
        s0 += __shfl_xor_sync(0xffffffffu, s0, 2);
        s1 += __shfl_xor_sync(0xffffffffu, s1, 1);
        s1 += __shfl_xor_sync(0xffffffffu, s1, 2);
        if (tq == 0) {
            g_partial[((size_t)bS + rr) * 32 + bx * 4 + wc]     = s0;
            g_partial[((size_t)bS + rr + 8) * 32 + bx * 4 + wc] = s1;
        }
    }

    if (offdiag) {
        #pragma unroll
        for (int nt = 0; nt < 4; nt++) {
            #pragma unroll
            for (int h = 0; h < 2; h++) {
                float v = cs[nt][h];
                v += __shfl_xor_sync(0xffffffffu, v, 4);
                v += __shfl_xor_sync(0xffffffffu, v, 8);
                v += __shfl_xor_sync(0xffffffffu, v, 16);
                cs[nt][h] = v;
            }
        }
        if (qid == 0) {
            #pragma unroll
            for (int nt = 0; nt < 4; nt++) {
                const int cc = colBase + nBase + nt * 8 + tq * 2;
                g_partial[((size_t)bS + cc) * 32 + by * 4 + wr]         = cs[nt][0];
                g_partial[((size_t)bS + cc + 1) * 32 + by * 4 + wr]     = cs[nt][1];
                g_partial[((size_t)bS + cc) * 32 + by * 4 + 2 + wr]     = 0.f;
                g_partial[((size_t)bS + cc + 1) * 32 + by * 4 + 2 + wr] = 0.f;
            }
        }
        __syncthreads();
        #pragma unroll
        for (int l = 0; l < 16; l++) {
            int idx = tid + l * 256;
            int c   = idx >> 5;
            int r4  = (idx & 31) << 2;
            float4 v = *(float4*)&stage[c * PADT + r4];
            *(float4*)&g_E[((size_t)bS + colBase + c) * SEQ + rowBase + r4] = v;
        }
    }
}

// ---------------------------------------------------------------------------
__global__ void reduce_den_kernel()
{
    int i = blockIdx.x * blockDim.x + threadIdx.x;
    if (i < BATCH * SEQ) {
        float s = EPS_F;
        #pragma unroll
        for (int j = 0; j < 32; j++) s += g_partial[(size_t)i * 32 + j];
        g_den[i] = s;
    }
}

// ---------------------------------------------------------------------------
// Kernel 3: out = (E @ A) / den.  128x128 block, 64x32 warp tile, 2 CTAs/SM,
// 3 stages.  E swizzled + LDS.64 (conflict-free), V [k][n] PADN=140 with
// k-rows permuted at cp.async source; epilogue un-permutes output columns.
// ---------------------------------------------------------------------------
__global__ void __launch_bounds__(256, 2) pv_mma(float* __restrict__ out)
{
    extern __shared__ float dsm[];

    const int b       = blockIdx.z;
    const int rowBase = blockIdx.y * 128;
    const int colBase = blockIdx.x * 128;
    const float* Ab = g_Atf + (size_t)b * SEQ * DIM;
    const float* Eb = g_E   + (size_t)b * SEQ * SEQ;
    const int bS = b * SEQ;

    const int tid  = threadIdx.x;
    const int wid  = tid >> 5;
    const int lane = tid & 31;
    const int qid  = lane >> 2;
    const int tq   = lane & 3;
    const int mBase = (wid >> 2) * 64;
    const int nBase = (wid & 3) * 32;

    const uint32_t cb  = (uint32_t)(tq >> 1);
    const uint32_t w8  = (uint32_t)((tq & 1) * 8);
    const uint32_t swz = (uint32_t)((qid & 3) << 1);

    const uint32_t sb = smem_u32(dsm);

    // E loader: 4 chunks/thread (128 rows x 8 chunks, swizzled)
    const float* gE[4]; uint32_t dstE[4];
    #pragma unroll
    for (int l = 0; l < 4; l++) {
        int idx = tid + l * 256;
        int r   = idx >> 3;
        int c   = idx & 7;
        dstE[l] = (uint32_t)(r * 128 + ((c ^ ((r & 3) << 1)) << 4));
        gE[l]   = Eb + (size_t)(rowBase + r) * SEQ + c * 4;
    }
    // V loader: 4 chunks/thread (32 rows x 32 chunks), k-rows permuted at src.
    const float* gV[4]; uint32_t dstV[4];
    #pragma unroll
    for (int l = 0; l < 4; l++) {
        int idx = tid + l * 256;
        int vr  = idx >> 5;                    // 0..31
        int vc  = idx & 31;                    // 0..31 chunks
        int kk  = (vr & ~7) | ((vr >> 1) & 3) | ((vr & 1) << 2);  // invp
        gV[l]   = Ab + (size_t)kk * DIM + colBase + vc * 4;
        dstV[l] = (uint32_t)(PV_E_B + vr * (PADN * 4) + vc * 16);
    }

    float acc[4][4][4];
    #pragma unroll
    for (int i = 0; i < 4; i++)
        #pragma unroll
        for (int j = 0; j < 4; j++)
            #pragma unroll
            for (int k = 0; k < 4; k++) acc[i][j][k] = 0.f;

    const int NT = SEQ / 32;   // 32

    #pragma unroll
    for (int s = 0; s < PV_STAGES - 1; s++) {
        const uint32_t so = s * PV_STAGE_B;
        const int k0 = s * 32;
        #pragma unroll
        for (int l = 0; l < 4; l++) {
            cp16(sb + so + dstE[l], gE[l] + k0);
            cp16(sb + so + dstV[l], gV[l] + (size_t)k0 * DIM);
        }
        CP_COMMIT();
    }

    for (int it = 0; it < NT; it++) {
        CP_WAIT1();
        __syncthreads();
        {
            const int tn = it + 2;
            if (tn < NT) {
                const uint32_t so = (tn % PV_STAGES) * PV_STAGE_B;
                const int k0 = tn * 32;
                #pragma unroll
                for (int l = 0; l < 4; l++) {
                    cp16(sb + so + dstE[l], gE[l] + k0);
                    cp16(sb + so + dstV[l], gV[l] + (size_t)k0 * DIM);
                }
            }
            CP_COMMIT();
        }
        const char* Es = (const char*)dsm + (it % PV_STAGES) * PV_STAGE_B;
        const float* Vs = (const float*)(Es + PV_E_B);
        #pragma unroll
        for (int ks = 0; ks < 4; ks++) {
            uint32_t bf[4][2];
            #pragma unroll
            for (int nt = 0; nt < 4; nt++) {
                const uint32_t* bp = (const uint32_t*)Vs +
                    (ks * 8 + 2 * tq) * PADN + nBase + nt * 8 + qid;
                bf[nt][0] = bp[0]; bf[nt][1] = bp[PADN];
            }
            #pragma unroll
            for (int mt = 0; mt < 4; mt++) {
                const char* ap = Es + SWOFF(mBase + mt * 16 + qid, ks);
                uint2 aL = *(const uint2*)ap;
                uint2 aH = *(const uint2*)(ap + 8 * 128);
                #pragma unroll
                for (int nt = 0; nt < 4; nt++)
                    mma_tf32(acc[mt][nt], aL.x, aH.x, aL.y, aH.y, bf[nt][0], bf[nt][1]);
            }
        }
    }

    // Epilogue: scale by 1/den; un-permute columns (positions (2tq,2tq+1)
    // within each n8 tile hold real columns (tq, tq+4)).
    #pragma unroll
    for (int mt = 0; mt < 4; mt++) {
        const int rr = rowBase + mBase + mt * 16 + qid;
        const float inv0 = 1.0f / g_den[bS + rr];
        const float inv1 = 1.0f / g_den[bS + rr + 8];
        float* o0 = out + ((size_t)bS + rr) * DIM;
        float* o1 = out + ((size_t)bS + rr + 8) * DIM;
        #pragma unroll
        for (int nt = 0; nt < 4; nt++) {
            const int base = colBase + nBase + nt * 8;
            o0[base + tq]     = acc[mt][nt][0] * inv0;
            o0[base + tq + 4] = acc[mt][nt][1] * inv0;
            o1[base + tq]     = acc[mt][nt][2] * inv1;
            o1[base + tq + 4] = acc[mt][nt][3] * inv1;
        }
    }
}

// ---------------------------------------------------------------------------
extern "C" void kernel_launch(void* const* d_in, const int* in_sizes, int n_in,
                              void* d_out, int out_size)
{
    const float* A    = (const float*)d_in[0];
    const int*   mask = (const int*)d_in[1];
    float*       out  = (float*)d_out;

    cudaFuncSetAttribute(qk_exp_mma, cudaFuncAttributeMaxDynamicSharedMemorySize, QK_SMEM);
    cudaFuncSetAttribute(pv_mma,     cudaFuncAttributeMaxDynamicSharedMemorySize, PV_SMEM);

    const size_t nA = (size_t)BATCH * SEQ * DIM;
    cvt_kernel<<<(unsigned)((nA / 4 + 255) / 256), 256>>>(A);

    dim3 g1(SEQ / 128, SEQ / 128, BATCH);   // triangle via early exit
    qk_exp_mma<<<g1, 256, QK_SMEM>>>(mask);

    reduce_den_kernel<<<(BATCH * SEQ + 255) / 256, 256>>>();

    dim3 g2(DIM / 128, SEQ / 128, BATCH);   // 6 x 8 x 8
    pv_mma<<<g2, 256, PV_SMEM>>>(out);
}

// round 13
// speedup vs baseline: 1.2290x; 1.0381x over previous
#include <cuda_runtime.h>
#include <cstdint>

#define BATCH 8
#define SEQ   1024
#define DIM   768
#define EPS_F 1e-7f

// Both GEMMs: 128x128 block, 8 warps 64x32, BK=32, swizzled 32-word rows.
#define STAGES   3
#define STAGE_B  32768                      // A-op 16KB + B-op 16KB
#define SMEM_B   (STAGES * STAGE_B)         // 98304 -> 2 CTAs/SM
#define PADT 132                            // qk transpose-stage stride

// k-permutation within 8-groups: pos(k) = (k&3)*2 + (k>>2)
__device__ __forceinline__ int pcol(int c) {
    return (c & ~7) | (((c & 3) << 1) + ((c >> 2) & 1));
}

// Scratch (allocation-free rule: __device__ globals)
__device__ float g_Atf[(size_t)BATCH * SEQ * DIM];  // tf32, [S][D], D-permuted
__device__ float g_AT [(size_t)BATCH * DIM * SEQ];  // tf32, [D][S], S-permuted
__device__ float g_E[(size_t)BATCH * SEQ * SEQ];    // tf32 exp scores, col-permuted
__device__ float g_partial[(size_t)BATCH * SEQ * 32];
__device__ float g_den[(size_t)BATCH * SEQ];

__device__ __forceinline__ uint32_t smem_u32(const void* p) {
    uint32_t a;
    asm("{ .reg .u64 t; cvta.to.shared.u64 t, %1; cvt.u32.u64 %0, t; }" : "=r"(a) : "l"(p));
    return a;
}
__device__ __forceinline__ uint32_t f2tf(float x) {
    uint32_t u; asm("cvt.rna.tf32.f32 %0, %1;" : "=r"(u) : "f"(x)); return u;
}
__device__ __forceinline__ void mma_tf32(float c[4],
                                         uint32_t a0, uint32_t a1, uint32_t a2, uint32_t a3,
                                         uint32_t b0, uint32_t b1) {
    asm("mma.sync.aligned.m16n8k8.row.col.f32.tf32.tf32.f32 "
        "{%0,%1,%2,%3}, {%4,%5,%6,%7}, {%8,%9}, {%0,%1,%2,%3};"
        : "+f"(c[0]), "+f"(c[1]), "+f"(c[2]), "+f"(c[3])
        : "r"(a0), "r"(a1), "r"(a2), "r"(a3), "r"(b0), "r"(b1));
}
__device__ __forceinline__ void cp16(uint32_t saddr, const void* g) {
    asm volatile("cp.async.cg.shared.global [%0], [%1], 16;" :: "r"(saddr), "l"(g));
}
#define CP_COMMIT() asm volatile("cp.async.commit_group;" ::: "memory")
#define CP_WAIT1()  asm volatile("cp.async.wait_group 1;" ::: "memory")

// swizzled fragment byte-offset inside a [rows][32 words] tile
#define SWOFF(row, ks) \
    ((uint32_t)(row) * 128u + (uint32_t)((((2*(ks)) + cb) ^ swz) << 4) + w8)

// ---------------------------------------------------------------------------
// Shared compute core with one-step fragment software pipelining.
// AsBuf/BsBuf are const char* to swizzled 128-row x 32-word tiles.
// ---------------------------------------------------------------------------
#define COMPUTE_PIPE(AsBuf, BsBuf) do {                                       \
    uint2 bq[4], nbq[4];                                                      \
    _Pragma("unroll")                                                         \
    for (int nt = 0; nt < 4; nt++)                                            \
        bq[nt] = *(const uint2*)((BsBuf) + SWOFF(nBase + nt * 8 + qid, 0));   \
    _Pragma("unroll")                                                         \
    for (int ks = 0; ks < 4; ks++) {                                          \
        if (ks < 3) {                                                         \
            _Pragma("unroll")                                                 \
            for (int nt = 0; nt < 4; nt++)                                    \
                nbq[nt] = *(const uint2*)((BsBuf) +                           \
                    SWOFF(nBase + nt * 8 + qid, ks + 1));                     \
        }                                                                     \
        uint2 aL = *(const uint2*)((AsBuf) + SWOFF(mBase + qid, ks));         \
        uint2 aH = *(const uint2*)((AsBuf) + SWOFF(mBase + qid + 8, ks));     \
        _Pragma("unroll")                                                     \
        for (int mt = 0; mt < 4; mt++) {                                      \
            uint2 naL, naH;                                                   \
            if (mt < 3) {                                                     \
                naL = *(const uint2*)((AsBuf) +                               \
                    SWOFF(mBase + (mt + 1) * 16 + qid, ks));                  \
                naH = *(const uint2*)((AsBuf) +                               \
                    SWOFF(mBase + (mt + 1) * 16 + qid + 8, ks));              \
            }                                                                 \
            _Pragma("unroll")                                                 \
            for (int nt = 0; nt < 4; nt++)                                    \
                mma_tf32(acc[mt][nt], aL.x, aH.x, aL.y, aH.y,                 \
                         bq[nt].x, bq[nt].y);                                 \
            if (mt < 3) { aL = naL; aH = naH; }                               \
        }                                                                     \
        if (ks < 3) {                                                         \
            _Pragma("unroll")                                                 \
            for (int nt = 0; nt < 4; nt++) bq[nt] = nbq[nt];                  \
        }                                                                     \
    }                                                                         \
} while (0)

// ---------------------------------------------------------------------------
// Kernel 0: fused tf32 round + dual layout: g_Atf[s][pcol(d)] and
// g_AT[d][pcol(s)].  SMEM 33-stride transpose, conflict-free, coalesced.
// ---------------------------------------------------------------------------
__global__ void __launch_bounds__(256) cvt_trans_kernel(const float* __restrict__ A)
{
    __shared__ float tile[32][33];
    const int b  = blockIdx.z;
    const int d0 = blockIdx.x * 32;
    const int s0 = blockIdx.y * 32;
    const int tx = threadIdx.x;          // 0..31
    const int ty = threadIdx.y;          // 0..7
    const float* Ab = A + (size_t)b * SEQ * DIM;

    #pragma unroll
    for (int j = 0; j < 4; j++)
        tile[ty + 8 * j][tx] = Ab[(size_t)(s0 + ty + 8 * j) * DIM + d0 + tx];
    __syncthreads();

    const int ivx = (tx & ~7) | ((tx >> 1) & 3) | ((tx & 1) << 2);   // invp
    float* Fb = g_Atf + (size_t)b * SEQ * DIM;
    float* Tb = g_AT  + (size_t)b * DIM * SEQ;
    #pragma unroll
    for (int j = 0; j < 4; j++) {
        int r = ty + 8 * j;
        Fb[(size_t)(s0 + r) * DIM + d0 + tx] = __uint_as_float(f2tf(tile[r][ivx]));
        Tb[(size_t)(d0 + r) * SEQ + s0 + tx] = __uint_as_float(f2tf(tile[ivx][r]));
    }
}

// ---------------------------------------------------------------------------
// Kernel 1: E = exp(A A^T) * masks, symmetric (bx >= by).
// ---------------------------------------------------------------------------
__global__ void __launch_bounds__(256, 2) qk_exp_mma(const int* __restrict__ mask)
{
    extern __shared__ float dsm[];

    const int bx = blockIdx.x;
    const int by = blockIdx.y;
    if (bx < by) return;
    const bool offdiag = (bx > by);

    const int b       = blockIdx.z;
    const int rowBase = by * 128;
    const int colBase = bx * 128;
    const float* Ab = g_Atf + (size_t)b * SEQ * DIM;
    const int bS = b * SEQ;

    const int tid  = threadIdx.x;
    const int wid  = tid >> 5;
    const int lane = tid & 31;
    const int qid  = lane >> 2;
    const int tq   = lane & 3;
    const int mBase = (wid >> 2) * 64;
    const int nBase = (wid & 3) * 32;
    const int wr   = wid >> 2;
    const int wc   = wid & 3;

    const uint32_t cb  = (uint32_t)(tq >> 1);
    const uint32_t w8  = (uint32_t)((tq & 1) * 8);
    const uint32_t swz = (uint32_t)((qid & 3) << 1);

    const uint32_t sb = smem_u32(dsm);

    const float* gA[4]; const float* gB[4]; uint32_t dstT[4];
    #pragma unroll
    for (int l = 0; l < 4; l++) {
        int idx = tid + l * 256;
        int r   = idx >> 3;
        int c   = idx & 7;
        dstT[l] = (uint32_t)(r * 128 + ((c ^ ((r & 3) << 1)) << 4));
        gA[l]   = Ab + (size_t)(rowBase + r) * DIM + c * 4;
        gB[l]   = Ab + (size_t)(colBase + r) * DIM + c * 4;
    }

    float acc[4][4][4];
    #pragma unroll
    for (int i = 0; i < 4; i++)
        #pragma unroll
        for (int j = 0; j < 4; j++)
            #pragma unroll
            for (int k = 0; k < 4; k++) acc[i][j][k] = 0.f;

    const int NT = DIM / 32;   // 24

    #pragma unroll
    for (int s = 0; s < STAGES - 1; s++) {
        const uint32_t so = s * STAGE_B;
        const int k0 = s * 32;
        #pragma unroll
        for (int l = 0; l < 4; l++) {
            cp16(sb + so + dstT[l], gA[l] + k0);
            cp16(sb + so + 16384 + dstT[l], gB[l] + k0);
        }
        CP_COMMIT();
    }

    for (int it = 0; it < NT; it++) {
        CP_WAIT1();
        __syncthreads();
        {
            const int tn = it + 2;
            if (tn < NT) {
                const uint32_t so = (tn % STAGES) * STAGE_B;
                const int k0 = tn * 32;
                #pragma unroll
                for (int l = 0; l < 4; l++) {
                    cp16(sb + so + dstT[l], gA[l] + k0);
                    cp16(sb + so + 16384 + dstT[l], gB[l] + k0);
                }
            }
            CP_COMMIT();
        }
        const char* As = (const char*)dsm + (it % STAGES) * STAGE_B;
        const char* Bs = As + 16384;
        COMPUTE_PIPE(As, Bs);
    }

    __syncthreads();
    float* stage = dsm;

    float cs[4][2];
    #pragma unroll
    for (int nt = 0; nt < 4; nt++) { cs[nt][0] = 0.f; cs[nt][1] = 0.f; }

    #pragma unroll
    for (int mt = 0; mt < 4; mt++) {
        const int rrl = mBase + mt * 16 + qid;
        const int rr  = rowBase + rrl;
        const int prr = pcol(rrl);
        const float mr0 = (float)mask[bS + rr];
        const float mr1 = (float)mask[bS + rr + 8];
        float s0 = 0.f, s1 = 0.f;
        #pragma unroll
        for (int nt = 0; nt < 4; nt++) {
            const int ccl = nBase + nt * 8 + tq * 2;
            const int cc  = colBase + ccl;
            const float mc0 = (float)mask[bS + cc];
            const float mc1 = (float)mask[bS + cc + 1];
            float e00 = __uint_as_float(f2tf(__expf(acc[mt][nt][0]) * mr0 * mc0));
            float e01 = __uint_as_float(f2tf(__expf(acc[mt][nt][1]) * mr0 * mc1));
            float e10 = __uint_as_float(f2tf(__expf(acc[mt][nt][2]) * mr1 * mc0));
            float e11 = __uint_as_float(f2tf(__expf(acc[mt][nt][3]) * mr1 * mc1));
            s0 += e00 + e01;
            s1 += e10 + e11;
            const int pc = colBase + pcol(ccl);
            float* er0 = &g_E[((size_t)bS + rr) * SEQ + pc];
            float* er1 = &g_E[((size_t)bS + rr + 8) * SEQ + pc];
            er0[0] = e00; er0[2] = e01;
            er1[0] = e10; er1[2] = e11;
            if (offdiag) {
                cs[nt][0] += e00 + e10;
                cs[nt][1] += e01 + e11;
                stage[ccl * PADT + prr]           = e00;
                stage[(ccl + 1) * PADT + prr]     = e01;
                stage[ccl * PADT + prr + 8]       = e10;
                stage[(ccl + 1) * PADT + prr + 8] = e11;
            }
        }
        s0 += __shfl_xor_sync(0xffffffffu, s0, 1);
        s0 += __shfl_xor_sync(0xffffffffu, s0, 2);
        s1 += __shfl_xor_sync(0xffffffffu, s1, 1);
        s1 += __shfl_xor_sync(0xffffffffu, s1, 2);
        if (tq == 0) {
            g_partial[((size_t)bS + rr) * 32 + bx * 4 + wc]     = s0;
            g_partial[((size_t)bS + rr + 8) * 32 + bx * 4 + wc] = s1;
        }
    }

    if (offdiag) {
        #pragma unroll
        for (int nt = 0; nt < 4; nt++) {
            #pragma unroll
            for (int h = 0; h < 2; h++) {
                float v = cs[nt][h];
                v += __shfl_xor_sync(0xffffffffu, v, 4);
                v += __shfl_xor_sync(0xffffffffu, v, 8);
                v += __shfl_xor_sync(0xffffffffu, v, 16);
                cs[nt][h] = v;
            }
        }
        if (qid == 0) {
            #pragma unroll
            for (int nt = 0; nt < 4; nt++) {
                const int cc = colBase + nBase + nt * 8 + tq * 2;
                g_partial[((size_t)bS + cc) * 32 + by * 4 + wr]         = cs[nt][0];
                g_partial[((size_t)bS + cc + 1) * 32 + by * 4 + wr]     = cs[nt][1];
                g_partial[((size_t)bS + cc) * 32 + by * 4 + 2 + wr]     = 0.f;
                g_partial[((size_t)bS + cc + 1) * 32 + by * 4 + 2 + wr] = 0.f;
            }
        }
        __syncthreads();
        #pragma unroll
        for (int l = 0; l < 16; l++) {
            int idx = tid + l * 256;
            int c   = idx >> 5;
            int r4  = (idx & 31) << 2;
            float4 v = *(float4*)&stage[c * PADT + r4];
            *(float4*)&g_E[((size_t)bS + colBase + c) * SEQ + rowBase + r4] = v;
        }
    }
}

// ---------------------------------------------------------------------------
__global__ void reduce_den_kernel()
{
    int i = blockIdx.x * blockDim.x + threadIdx.x;
    if (i < BATCH * SEQ) {
        float s = EPS_F;
        #pragma unroll
        for (int j = 0; j < 32; j++) s += g_partial[(size_t)i * 32 + j];
        g_den[i] = s;
    }
}

// ---------------------------------------------------------------------------
// Kernel 3: out = (E @ A) / den.  V from g_AT (K-major, s-permuted) -> fully
// isomorphic to qk mainloop (all swizzled LDS.64 frags).  No un-permute.
// ---------------------------------------------------------------------------
__global__ void __launch_bounds__(256, 2) pv_mma(float* __restrict__ out)
{
    extern __shared__ float dsm[];

    const int b       = blockIdx.z;
    const int rowBase = blockIdx.y * 128;
    const int colBase = blockIdx.x * 128;
    const float* ATb = g_AT + (size_t)b * DIM * SEQ;
    const float* Eb  = g_E  + (size_t)b * SEQ * SEQ;
    const int bS = b * SEQ;

    const int tid  = threadIdx.x;
    const int wid  = tid >> 5;
    const int lane = tid & 31;
    const int qid  = lane >> 2;
    const int tq   = lane & 3;
    const int mBase = (wid >> 2) * 64;
    const int nBase = (wid & 3) * 32;

    const uint32_t cb  = (uint32_t)(tq >> 1);
    const uint32_t w8  = (uint32_t)((tq & 1) * 8);
    const uint32_t swz = (uint32_t)((qid & 3) << 1);

    const uint32_t sb = smem_u32(dsm);

    const float* gE[4]; const float* gV[4]; uint32_t dstT[4];
    #pragma unroll
    for (int l = 0; l < 4; l++) {
        int idx = tid + l * 256;
        int r   = idx >> 3;
        int c   = idx & 7;
        dstT[l] = (uint32_t)(r * 128 + ((c ^ ((r & 3) << 1)) << 4));
        gE[l]   = Eb  + (size_t)(rowBase + r) * SEQ + c * 4;
        gV[l]   = ATb + (size_t)(colBase + r) * SEQ + c * 4;
    }

    float acc[4][4][4];
    #pragma unroll
    for (int i = 0; i < 4; i++)
        #pragma unroll
        for (int j = 0; j < 4; j++)
            #pragma unroll
            for (int k = 0; k < 4; k++) acc[i][j][k] = 0.f;

    const int NT = SEQ / 32;   // 32

    #pragma unroll
    for (int s = 0; s < STAGES - 1; s++) {
        const uint32_t so = s * STAGE_B;
        const int k0 = s * 32;
        #pragma unroll
        for (int l = 0; l < 4; l++) {
            cp16(sb + so + dstT[l], gE[l] + k0);
            cp16(sb + so + 16384 + dstT[l], gV[l] + k0);
        }
        CP_COMMIT();
    }

    for (int it = 0; it < NT; it++) {
        CP_WAIT1();
        __syncthreads();
        {
            const int tn = it + 2;
            if (tn < NT) {
                const uint32_t so = (tn % STAGES) * STAGE_B;
                const int k0 = tn * 32;
                #pragma unroll
                for (int l = 0; l < 4; l++) {
                    cp16(sb + so + dstT[l], gE[l] + k0);
                    cp16(sb + so + 16384 + dstT[l], gV[l] + k0);
                }
            }
            CP_COMMIT();
        }
        const char* Es = (const char*)dsm + (it % STAGES) * STAGE_B;
        const char* Vs = Es + 16384;
        COMPUTE_PIPE(Es, Vs);
    }

    // Epilogue: scale by 1/den; columns are real (consecutive pairs).
    #pragma unroll
    for (int mt = 0; mt < 4; mt++) {
        const int rr = rowBase + mBase + mt * 16 + qid;
        const float inv0 = 1.0f / g_den[bS + rr];
        const float inv1 = 1.0f / g_den[bS + rr + 8];
        #pragma unroll
        for (int nt = 0; nt < 4; nt++) {
            const int cc = colBase + nBase + nt * 8 + tq * 2;
            *(float2*)&out[((size_t)bS + rr) * DIM + cc] =
                make_float2(acc[mt][nt][0] * inv0, acc[mt][nt][1] * inv0);
            *(float2*)&out[((size_t)bS + rr + 8) * DIM + cc] =
                make_float2(acc[mt][nt][2] * inv1, acc[mt][nt][3] * inv1);
        }
    }
}

// ---------------------------------------------------------------------------
extern "C" void kernel_launch(void* const* d_in, const int* in_sizes, int n_in,
                              void* d_out, int out_size)
{
    const float* A    = (const float*)d_in[0];
    const int*   mask = (const int*)d_in[1];
    float*       out  = (float*)d_out;

    cudaFuncSetAttribute(qk_exp_mma, cudaFuncAttributeMaxDynamicSharedMemorySize, SMEM_B);
    cudaFuncSetAttribute(pv_mma,     cudaFuncAttributeMaxDynamicSharedMemorySize, SMEM_B);

    dim3 gc(DIM / 32, SEQ / 32, BATCH);     // 24 x 32 x 8
    cvt_trans_kernel<<<gc, dim3(32, 8)>>>(A);

    dim3 g1(SEQ / 128, SEQ / 128, BATCH);   // triangle via early exit
    qk_exp_mma<<<g1, 256, SMEM_B>>>(mask);

    reduce_den_kernel<<<(BATCH * SEQ + 255) / 256, 256>>>();

    dim3 g2(DIM / 128, SEQ / 128, BATCH);   // 6 x 8 x 8
    pv_mma<<<g2, 256, SMEM_B>>>(out);
}

// round 15
// speedup vs baseline: 1.2668x; 1.0308x over previous
#include <cuda_runtime.h>
#include <cstdint>

#define BATCH 8
#define SEQ   1024
#define DIM   768
#define EPS_F 1e-7f

// Both GEMMs: 128x128 block, 8 warps 64x32, BK=32, swizzled 32-word rows.
#define STAGES   3
#define STAGE_B  32768                      // A-op 16KB + B-op 16KB
#define SMEM_B   (STAGES * STAGE_B)         // 98304
#define PV_SMEM  (SMEM_B + 512)             // + den[128]
#define PADT 132                            // qk transpose-stage stride

// k-permutation within 8-groups: pos(k) = (k&3)*2 + (k>>2)
__device__ __forceinline__ int pcol(int c) {
    return (c & ~7) | (((c & 3) << 1) + ((c >> 2) & 1));
}

// Scratch (allocation-free rule: __device__ globals)
__device__ float g_Atf[(size_t)BATCH * SEQ * DIM];  // tf32, [S][D], D-permuted
__device__ float g_AT [(size_t)BATCH * DIM * SEQ];  // tf32, [D][S], S-permuted
__device__ float g_E[(size_t)BATCH * SEQ * SEQ];    // tf32 exp scores, col-permuted
__device__ float g_partial[(size_t)BATCH * SEQ * 32];

__device__ __forceinline__ uint32_t smem_u32(const void* p) {
    uint32_t a;
    asm("{ .reg .u64 t; cvta.to.shared.u64 t, %1; cvt.u32.u64 %0, t; }" : "=r"(a) : "l"(p));
    return a;
}
__device__ __forceinline__ uint32_t f2tf(float x) {
    uint32_t u; asm("cvt.rna.tf32.f32 %0, %1;" : "=r"(u) : "f"(x)); return u;
}
__device__ __forceinline__ void mma_tf32(float c[4],
                                         uint32_t a0, uint32_t a1, uint32_t a2, uint32_t a3,
                                         uint32_t b0, uint32_t b1) {
    asm("mma.sync.aligned.m16n8k8.row.col.f32.tf32.tf32.f32 "
        "{%0,%1,%2,%3}, {%4,%5,%6,%7}, {%8,%9}, {%0,%1,%2,%3};"
        : "+f"(c[0]), "+f"(c[1]), "+f"(c[2]), "+f"(c[3])
        : "r"(a0), "r"(a1), "r"(a2), "r"(a3), "r"(b0), "r"(b1));
}
__device__ __forceinline__ void cp16(uint32_t saddr, const void* g) {
    asm volatile("cp.async.cg.shared.global [%0], [%1], 16;" :: "r"(saddr), "l"(g));
}
#define CP_COMMIT() asm volatile("cp.async.commit_group;" ::: "memory")
#define CP_WAIT1()  asm volatile("cp.async.wait_group 1;" ::: "memory")

// swizzled fragment byte-offset inside a [rows][32 words] tile
#define SWOFF(row, ks) \
    ((uint32_t)(row) * 128u + (uint32_t)((((2*(ks)) + cb) ^ swz) << 4) + w8)

// ---------------------------------------------------------------------------
// Shared compute core with one-step fragment software pipelining.
// ---------------------------------------------------------------------------
#define COMPUTE_PIPE(AsBuf, BsBuf) do {                                       \
    uint2 bq[4], nbq[4];                                                      \
    _Pragma("unroll")                                                         \
    for (int nt = 0; nt < 4; nt++)                                            \
        bq[nt] = *(const uint2*)((BsBuf) + SWOFF(nBase + nt * 8 + qid, 0));   \
    _Pragma("unroll")                                                         \
    for (int ks = 0; ks < 4; ks++) {                                          \
        if (ks < 3) {                                                         \
            _Pragma("unroll")                                                 \
            for (int nt = 0; nt < 4; nt++)                                    \
                nbq[nt] = *(const uint2*)((BsBuf) +                           \
                    SWOFF(nBase + nt * 8 + qid, ks + 1));                     \
        }                                                                     \
        uint2 aL = *(const uint2*)((AsBuf) + SWOFF(mBase + qid, ks));         \
        uint2 aH = *(const uint2*)((AsBuf) + SWOFF(mBase + qid + 8, ks));     \
        _Pragma("unroll")                                                     \
        for (int mt = 0; mt < 4; mt++) {                                      \
            uint2 naL, naH;                                                   \
            if (mt < 3) {                                                     \
                naL = *(const uint2*)((AsBuf) +                               \
                    SWOFF(mBase + (mt + 1) * 16 + qid, ks));                  \
                naH = *(const uint2*)((AsBuf) +                               \
                    SWOFF(mBase + (mt + 1) * 16 + qid + 8, ks));              \
            }                                                                 \
            _Pragma("unroll")                                                 \
            for (int nt = 0; nt < 4; nt++)                                    \
                mma_tf32(acc[mt][nt], aL.x, aH.x, aL.y, aH.y,                 \
                         bq[nt].x, bq[nt].y);                                 \
            if (mt < 3) { aL = naL; aH = naH; }                               \
        }                                                                     \
        if (ks < 3) {                                                         \
            _Pragma("unroll")                                                 \
            for (int nt = 0; nt < 4; nt++) bq[nt] = nbq[nt];                  \
        }                                                                     \
    }                                                                         \
} while (0)

// ---------------------------------------------------------------------------
// Kernel 0: fused tf32 round + dual layout: g_Atf[s][pcol(d)], g_AT[d][pcol(s)]
// ---------------------------------------------------------------------------
__global__ void __launch_bounds__(256) cvt_trans_kernel(const float* __restrict__ A)
{
    __shared__ float tile[32][33];
    const int b  = blockIdx.z;
    const int d0 = blockIdx.x * 32;
    const int s0 = blockIdx.y * 32;
    const int tx = threadIdx.x;
    const int ty = threadIdx.y;
    const float* Ab = A + (size_t)b * SEQ * DIM;

    #pragma unroll
    for (int j = 0; j < 4; j++)
        tile[ty + 8 * j][tx] = Ab[(size_t)(s0 + ty + 8 * j) * DIM + d0 + tx];
    __syncthreads();

    const int ivx = (tx & ~7) | ((tx >> 1) & 3) | ((tx & 1) << 2);   // invp
    float* Fb = g_Atf + (size_t)b * SEQ * DIM;
    float* Tb = g_AT  + (size_t)b * DIM * SEQ;
    #pragma unroll
    for (int j = 0; j < 4; j++) {
        int r = ty + 8 * j;
        Fb[(size_t)(s0 + r) * DIM + d0 + tx] = __uint_as_float(f2tf(tile[r][ivx]));
        Tb[(size_t)(d0 + r) * SEQ + s0 + tx] = __uint_as_float(f2tf(tile[ivx][r]));
    }
}

// ---------------------------------------------------------------------------
// Kernel 1: E = exp(A A^T) * masks, triangle-linearized grid (36 tiles/batch).
// Mainloop order (PROVEN): wait_group 1 -> sync -> issue(it+2) -> compute(it).
// ---------------------------------------------------------------------------
__global__ void __launch_bounds__(256, 2) qk_exp_mma(const int* __restrict__ mask)
{
    extern __shared__ float dsm[];

    // decode (by, bx) from linearized upper-triangle index
    int by = 0, rem = blockIdx.x;
    while (rem >= 8 - by) { rem -= 8 - by; by++; }
    const int bx = by + rem;
    const bool offdiag = (bx > by);

    const int b       = blockIdx.z;
    const int rowBase = by * 128;
    const int colBase = bx * 128;
    const float* Ab = g_Atf + (size_t)b * SEQ * DIM;
    const int bS = b * SEQ;

    const int tid  = threadIdx.x;
    const int wid  = tid >> 5;
    const int lane = tid & 31;
    const int qid  = lane >> 2;
    const int tq   = lane & 3;
    const int mBase = (wid >> 2) * 64;
    const int nBase = (wid & 3) * 32;
    const int wr   = wid >> 2;
    const int wc   = wid & 3;

    const uint32_t cb  = (uint32_t)(tq >> 1);
    const uint32_t w8  = (uint32_t)((tq & 1) * 8);
    const uint32_t swz = (uint32_t)((qid & 3) << 1);

    const uint32_t sb = smem_u32(dsm);

    const float* gA[4]; const float* gB[4]; uint32_t dstT[4];
    #pragma unroll
    for (int l = 0; l < 4; l++) {
        int idx = tid + l * 256;
        int r   = idx >> 3;
        int c   = idx & 7;
        dstT[l] = (uint32_t)(r * 128 + ((c ^ ((r & 3) << 1)) << 4));
        gA[l]   = Ab + (size_t)(rowBase + r) * DIM + c * 4;
        gB[l]   = Ab + (size_t)(colBase + r) * DIM + c * 4;
    }

    float acc[4][4][4];
    #pragma unroll
    for (int i = 0; i < 4; i++)
        #pragma unroll
        for (int j = 0; j < 4; j++)
            #pragma unroll
            for (int k = 0; k < 4; k++) acc[i][j][k] = 0.f;

    const int NT = DIM / 32;   // 24

    #pragma unroll
    for (int s = 0; s < STAGES - 1; s++) {
        const uint32_t so = s * STAGE_B;
        const int k0 = s * 32;
        #pragma unroll
        for (int l = 0; l < 4; l++) {
            cp16(sb + so + dstT[l], gA[l] + k0);
            cp16(sb + so + 16384 + dstT[l], gB[l] + k0);
        }
        CP_COMMIT();
    }

    for (int it = 0; it < NT; it++) {
        CP_WAIT1();                 // per-thread: tile it complete
        __syncthreads();            // collective: stage(it) published, stage(it-1) free
        {
            const int tn = it + 2;
            if (tn < NT) {
                const uint32_t so = (tn % STAGES) * STAGE_B;
                const int k0 = tn * 32;
                #pragma unroll
                for (int l = 0; l < 4; l++) {
                    cp16(sb + so + dstT[l], gA[l] + k0);
                    cp16(sb + so + 16384 + dstT[l], gB[l] + k0);
                }
            }
            CP_COMMIT();
        }
        const char* As = (const char*)dsm + (it % STAGES) * STAGE_B;
        const char* Bs = As + 16384;
        COMPUTE_PIPE(As, Bs);
    }

    __syncthreads();
    float* stage = dsm;

    float cs[4][2];
    #pragma unroll
    for (int nt = 0; nt < 4; nt++) { cs[nt][0] = 0.f; cs[nt][1] = 0.f; }

    #pragma unroll
    for (int mt = 0; mt < 4; mt++) {
        const int rrl = mBase + mt * 16 + qid;
        const int rr  = rowBase + rrl;
        const int prr = pcol(rrl);
        const float mr0 = (float)mask[bS + rr];
        const float mr1 = (float)mask[bS + rr + 8];
        float s0 = 0.f, s1 = 0.f;
        #pragma unroll
        for (int nt = 0; nt < 4; nt++) {
            const int ccl = nBase + nt * 8 + tq * 2;
            const int cc  = colBase + ccl;
            const float mc0 = (float)mask[bS + cc];
            const float mc1 = (float)mask[bS + cc + 1];
            float e00 = __uint_as_float(f2tf(__expf(acc[mt][nt][0]) * mr0 * mc0));
            float e01 = __uint_as_float(f2tf(__expf(acc[mt][nt][1]) * mr0 * mc1));
            float e10 = __uint_as_float(f2tf(__expf(acc[mt][nt][2]) * mr1 * mc0));
            float e11 = __uint_as_float(f2tf(__expf(acc[mt][nt][3]) * mr1 * mc1));
            s0 += e00 + e01;
            s1 += e10 + e11;
            const int pc = colBase + pcol(ccl);
            float* er0 = &g_E[((size_t)bS + rr) * SEQ + pc];
            float* er1 = &g_E[((size_t)bS + rr + 8) * SEQ + pc];
            er0[0] = e00; er0[2] = e01;
            er1[0] = e10; er1[2] = e11;
            if (offdiag) {
                cs[nt][0] += e00 + e10;
                cs[nt][1] += e01 + e11;
                stage[ccl * PADT + prr]           = e00;
                stage[(ccl + 1) * PADT + prr]     = e01;
                stage[ccl * PADT + prr + 8]       = e10;
                stage[(ccl + 1) * PADT + prr + 8] = e11;
            }
        }
        s0 += __shfl_xor_sync(0xffffffffu, s0, 1);
        s0 += __shfl_xor_sync(0xffffffffu, s0, 2);
        s1 += __shfl_xor_sync(0xffffffffu, s1, 1);
        s1 += __shfl_xor_sync(0xffffffffu, s1, 2);
        if (tq == 0) {
            g_partial[((size_t)bS + rr) * 32 + bx * 4 + wc]     = s0;
            g_partial[((size_t)bS + rr + 8) * 32 + bx * 4 + wc] = s1;
        }
    }

    if (offdiag) {
        #pragma unroll
        for (int nt = 0; nt < 4; nt++) {
            #pragma unroll
            for (int h = 0; h < 2; h++) {
                float v = cs[nt][h];
                v += __shfl_xor_sync(0xffffffffu, v, 4);
                v += __shfl_xor_sync(0xffffffffu, v, 8);
                v += __shfl_xor_sync(0xffffffffu, v, 16);
                cs[nt][h] = v;
            }
        }
        if (qid == 0) {
            #pragma unroll
            for (int nt = 0; nt < 4; nt++) {
                const int cc = colBase + nBase + nt * 8 + tq * 2;
                g_partial[((size_t)bS + cc) * 32 + by * 4 + wr]         = cs[nt][0];
                g_partial[((size_t)bS + cc + 1) * 32 + by * 4 + wr]     = cs[nt][1];
                g_partial[((size_t)bS + cc) * 32 + by * 4 + 2 + wr]     = 0.f;
                g_partial[((size_t)bS + cc + 1) * 32 + by * 4 + 2 + wr] = 0.f;
            }
        }
        __syncthreads();
        #pragma unroll
        for (int l = 0; l < 16; l++) {
            int idx = tid + l * 256;
            int c   = idx >> 5;
            int r4  = (idx & 31) << 2;
            float4 v = *(float4*)&stage[c * PADT + r4];
            *(float4*)&g_E[((size_t)bS + colBase + c) * SEQ + rowBase + r4] = v;
        }
    }
}

// ---------------------------------------------------------------------------
// Kernel 2: out = (E @ A) / den.  Denominators folded into prologue (SMEM);
// mainloop order identical to the proven round-13 structure.
// ---------------------------------------------------------------------------
__global__ void __launch_bounds__(256, 2) pv_mma(float* __restrict__ out)
{
    extern __shared__ float dsm[];
    float* den_s = dsm + SMEM_B / 4;        // 128 floats after the stages

    const int b       = blockIdx.z;
    const int rowBase = blockIdx.y * 128;
    const int colBase = blockIdx.x * 128;
    const float* ATb = g_AT + (size_t)b * DIM * SEQ;
    const float* Eb  = g_E  + (size_t)b * SEQ * SEQ;
    const int bS = b * SEQ;

    const int tid  = threadIdx.x;
    const int wid  = tid >> 5;
    const int lane = tid & 31;
    const int qid  = lane >> 2;
    const int tq   = lane & 3;
    const int mBase = (wid >> 2) * 64;
    const int nBase = (wid & 3) * 32;

    const uint32_t cb  = (uint32_t)(tq >> 1);
    const uint32_t w8  = (uint32_t)((tq & 1) * 8);
    const uint32_t swz = (uint32_t)((qid & 3) << 1);

    const uint32_t sb = smem_u32(dsm);

    const float* gE[4]; const float* gV[4]; uint32_t dstT[4];
    #pragma unroll
    for (int l = 0; l < 4; l++) {
        int idx = tid + l * 256;
        int r   = idx >> 3;
        int c   = idx & 7;
        dstT[l] = (uint32_t)(r * 128 + ((c ^ ((r & 3) << 1)) << 4));
        gE[l]   = Eb  + (size_t)(rowBase + r) * SEQ + c * 4;
        gV[l]   = ATb + (size_t)(colBase + r) * SEQ + c * 4;
    }

    // prologue cp.async first (loads in flight), then fold the denominator
    #pragma unroll
    for (int s = 0; s < STAGES - 1; s++) {
        const uint32_t so = s * STAGE_B;
        const int k0 = s * 32;
        #pragma unroll
        for (int l = 0; l < 4; l++) {
            cp16(sb + so + dstT[l], gE[l] + k0);
            cp16(sb + so + 16384 + dstT[l], gV[l] + k0);
        }
        CP_COMMIT();
    }

    // denominator: 2 threads per row, 16 partials each, pair-combine via shfl.
    // Published to all threads by the first mainloop __syncthreads.
    {
        const int row = tid >> 1;               // 0..127
        const int h   = tid & 1;
        const float* p = g_partial + ((size_t)bS + rowBase + row) * 32 + h * 16;
        float s = 0.f;
        #pragma unroll
        for (int j = 0; j < 16; j++) s += p[j];
        s += __shfl_xor_sync(0xffffffffu, s, 1);
        if (h == 0) den_s[row] = s + EPS_F;
    }

    float acc[4][4][4];
    #pragma unroll
    for (int i = 0; i < 4; i++)
        #pragma unroll
        for (int j = 0; j < 4; j++)
            #pragma unroll
            for (int k = 0; k < 4; k++) acc[i][j][k] = 0.f;

    const int NT = SEQ / 32;   // 32

    for (int it = 0; it < NT; it++) {
        CP_WAIT1();
        __syncthreads();
        {
            const int tn = it + 2;
            if (tn < NT) {
                const uint32_t so = (tn % STAGES) * STAGE_B;
                const int k0 = tn * 32;
                #pragma unroll
                for (int l = 0; l < 4; l++) {
                    cp16(sb + so + dstT[l], gE[l] + k0);
                    cp16(sb + so + 16384 + dstT[l], gV[l] + k0);
                }
            }
            CP_COMMIT();
        }
        const char* Es = (const char*)dsm + (it % STAGES) * STAGE_B;
        const char* Vs = Es + 16384;
        COMPUTE_PIPE(Es, Vs);
    }

    // Epilogue: scale by 1/den (from SMEM), coalesced float2 stores.
    #pragma unroll
    for (int mt = 0; mt < 4; mt++) {
        const int rl = mBase + mt * 16 + qid;
        const int rr = rowBase + rl;
        const float inv0 = 1.0f / den_s[rl];
        const float inv1 = 1.0f / den_s[rl + 8];
        #pragma unroll
        for (int nt = 0; nt < 4; nt++) {
            const int cc = colBase + nBase + nt * 8 + tq * 2;
            *(float2*)&out[((size_t)bS + rr) * DIM + cc] =
                make_float2(acc[mt][nt][0] * inv0, acc[mt][nt][1] * inv0);
            *(float2*)&out[((size_t)bS + rr + 8) * DIM + cc] =
                make_float2(acc[mt][nt][2] * inv1, acc[mt][nt][3] * inv1);
        }
    }
}

// ---------------------------------------------------------------------------
extern "C" void kernel_launch(void* const* d_in, const int* in_sizes, int n_in,
                              void* d_out, int out_size)
{
    const float* A    = (const float*)d_in[0];
    const int*   mask = (const int*)d_in[1];
    float*       out  = (float*)d_out;

    cudaFuncSetAttribute(qk_exp_mma, cudaFuncAttributeMaxDynamicSharedMemorySize, SMEM_B);
    cudaFuncSetAttribute(pv_mma,     cudaFuncAttributeMaxDynamicSharedMemorySize, PV_SMEM);

    dim3 gc(DIM / 32, SEQ / 32, BATCH);     // 24 x 32 x 8
    cvt_trans_kernel<<<gc, dim3(32, 8)>>>(A);

    dim3 g1(36, 1, BATCH);                  // linearized upper triangle
    qk_exp_mma<<<g1, 256, SMEM_B>>>(mask);

    dim3 g2(DIM / 128, SEQ / 128, BATCH);   // 6 x 8 x 8
    pv_mma<<<g2, 256, PV_SMEM>>>(out);
}